// round 2
// baseline (speedup 1.0000x reference)
#include <cuda_runtime.h>

// MultiScaleTrendDirectionLoss — fused EMA + sign-mismatch masked MSE.
// pred, target: [32, 8192, 64] fp32. Output: scalar fp32.
//
// Strategy: chunk the T axis (CHUNK=256) with a HALO=128 warm-up so chunks are
// independent ((0.9)^128 ~ 1.4e-6 state error, far below the 1e-3 tolerance).
// One warp per (batch, chunk) row; each thread owns 2 d-lanes via float2 so
// every warp load is one coalesced 256B LDG.64. 1024 blocks x 32 threads keeps
// ~7 warps/SM resident in a single wave.

#define Bn 32
#define Tn 8192
#define Dn 64
#define CHUNK 256
#define HALO 128
#define NCHUNK (Tn / CHUNK)   // 32
#define NROWS (Bn * NCHUNK)   // 1024

__device__ float g_partial[NROWS];

__global__ __launch_bounds__(32) void msl_main(const float* __restrict__ pred,
                                               const float* __restrict__ tgt)
{
    const int lane = threadIdx.x;          // 0..31 -> d pair {2*lane, 2*lane+1}
    const int row  = blockIdx.x;           // (b, chunk)
    const int b  = row >> 5;               // row / NCHUNK  (NCHUNK == 32)
    const int c  = row & 31;               // row % NCHUNK
    const int cs = c * CHUNK;
    const int t0 = (c == 0) ? 0 : (cs - HALO);

    // float2 view: element (b, t, dpair=lane) at index (b*Tn + t)*32 + lane
    const float2* __restrict__ pp =
        reinterpret_cast<const float2*>(pred) + (size_t)b * Tn * (Dn / 2) + (size_t)t0 * (Dn / 2) + lane;
    const float2* __restrict__ qq =
        reinterpret_cast<const float2*>(tgt)  + (size_t)b * Tn * (Dn / 2) + (size_t)t0 * (Dn / 2) + lane;

    const float ALPHA[3] = {0.1f, 0.3f, 0.5f};

    // Init EMA state from the element at t0 (exact for chunk 0; warm-up seed otherwise)
    float2 x0 = *pp;
    float2 y0 = *qq;
    float pe[3][2], te[3][2], acc[3];
#pragma unroll
    for (int k = 0; k < 3; ++k) {
        pe[k][0] = x0.x; pe[k][1] = x0.y;
        te[k][0] = y0.x; te[k][1] = y0.y;
        acc[k] = 0.0f;
    }

    pp += Dn / 2;  // advance to t0 + 1
    qq += Dn / 2;

    // ---- Warm-up: t in (t0, cs), no accumulation (127 iters for c>0, none for c==0)
#pragma unroll 8
    for (int t = t0 + 1; t < cs; ++t, pp += Dn / 2, qq += Dn / 2) {
        float2 xv = *pp;
        float2 yv = *qq;
#pragma unroll
        for (int k = 0; k < 3; ++k) {
            pe[k][0] = fmaf(ALPHA[k], xv.x - pe[k][0], pe[k][0]);
            pe[k][1] = fmaf(ALPHA[k], xv.y - pe[k][1], pe[k][1]);
            te[k][0] = fmaf(ALPHA[k], yv.x - te[k][0], te[k][0]);
            te[k][1] = fmaf(ALPHA[k], yv.y - te[k][1], te[k][1]);
        }
    }

    // ---- Accumulation: t in [tbeg, cs + CHUNK)
    // sign(pe_t - pe_{t-1}) == sign(x_t - pe_{t-1}) since alpha > 0, so the
    // mismatch test is just dx*dy < 0 on the FMA operands.
    const int tbeg = (c == 0) ? 1 : cs;
    const int tend = cs + CHUNK;
#pragma unroll 8
    for (int t = tbeg; t < tend; ++t, pp += Dn / 2, qq += Dn / 2) {
        float2 xv = *pp;
        float2 yv = *qq;
#pragma unroll
        for (int k = 0; k < 3; ++k) {
            float dx0 = xv.x - pe[k][0], dy0 = yv.x - te[k][0];
            float dx1 = xv.y - pe[k][1], dy1 = yv.y - te[k][1];
            pe[k][0] = fmaf(ALPHA[k], dx0, pe[k][0]);
            te[k][0] = fmaf(ALPHA[k], dy0, te[k][0]);
            pe[k][1] = fmaf(ALPHA[k], dx1, pe[k][1]);
            te[k][1] = fmaf(ALPHA[k], dy1, te[k][1]);
            float e0 = pe[k][0] - te[k][0];
            float e1 = pe[k][1] - te[k][1];
            if (dx0 * dy0 < 0.0f) acc[k] = fmaf(e0, e0, acc[k]);
            if (dx1 * dy1 < 0.0f) acc[k] = fmaf(e1, e1, acc[k]);
        }
    }

    // Weighted per-thread sum, warp tree-reduce, one partial per row.
    float local = 0.5f * acc[0] + 0.3f * acc[1] + 0.2f * acc[2];
#pragma unroll
    for (int off = 16; off > 0; off >>= 1)
        local += __shfl_down_sync(0xffffffffu, local, off);
    if (lane == 0) g_partial[row] = local;
}

// Deterministic fixed-order tree reduction of the 1024 row partials.
__global__ void msl_reduce(float* __restrict__ out)
{
    __shared__ float s[NROWS];
    int i = threadIdx.x;
    s[i] = g_partial[i];
    __syncthreads();
#pragma unroll
    for (int off = NROWS / 2; off > 0; off >>= 1) {
        if (i < off) s[i] += s[i + off];
        __syncthreads();
    }
    if (i == 0)
        out[0] = s[0] * (1.0f / (8191.0f * 2048.0f));  // mean over T-1 then over B*D
}

extern "C" void kernel_launch(void* const* d_in, const int* in_sizes, int n_in,
                              void* d_out, int out_size)
{
    const float* pred = (const float*)d_in[0];
    const float* tgt  = (const float*)d_in[1];
    msl_main<<<NROWS, 32>>>(pred, tgt);
    msl_reduce<<<1, NROWS>>>((float*)d_out);
}